// round 6
// baseline (speedup 1.0000x reference)
#include <cuda_runtime.h>
#include <cfloat>

#define PH 7
#define PW 7
#define NN 4
#define CC 128
#define HH 50
#define WW 50
#define SCALE 0.0625f
#define MAXW 9   // max cells per bin in w: ceil((pw+1)*bw)-floor(pw*bw) < bw+2 <= 9.15

// channel-last scratch: [N][H][W][C], 5.12 MB
__device__ float g_featT[NN * HH * WW * CC];

// transpose [C,W] -> [W,C] per (b,h,c-half)
__global__ void transpose_kernel(const float* __restrict__ feat) {
    int blk = blockIdx.x;
    int b    = blk / (HH * 2);
    int rest = blk % (HH * 2);
    int h    = rest >> 1;
    int c0   = (rest & 1) * 64;

    __shared__ float tile[64 * WW];  // 12.8 KB

    const float* src = feat + ((long)b * CC + c0) * (HH * WW) + h * WW;
    for (int i = threadIdx.x; i < 64 * WW; i += blockDim.x) {
        int c = i / WW;
        int w = i % WW;
        tile[i] = src[(long)c * (HH * WW) + w];
    }
    __syncthreads();
    float* dst = g_featT + ((long)(b * HH + h) * WW) * CC + c0;
    for (int i = threadIdx.x; i < 64 * WW; i += blockDim.x) {
        int w = i >> 6;
        int c = i & 63;
        dst[(long)w * CC + c] = tile[c * WW + w];
    }
}

// one block per (k, ph); 14 warps: warp = (chalf, pw); lane = 2 channels (float2)
__global__ __launch_bounds__(448) void roipool_kernel(const float* __restrict__ rois,
                                                      float* __restrict__ out) {
    int k  = blockIdx.x / PH;
    int ph = blockIdx.x % PH;
    int wid  = threadIdx.x >> 5;   // 0..13
    int lane = threadIdx.x & 31;
    int pw    = wid % PW;
    int chalf = wid / PW;          // 0 or 1

    __shared__ float so[PW * CC];  // [pw][c], 3.5 KB

    const float* r = rois + k * 5;
    int b  = (int)__ldg(r + 0);
    int x1 = (int)rintf(__ldg(r + 1) * SCALE);
    int y1 = (int)rintf(__ldg(r + 2) * SCALE);
    int x2 = (int)rintf(__ldg(r + 3) * SCALE);
    int y2 = (int)rintf(__ldg(r + 4) * SCALE);

    float roi_w = (float)max(x2 - x1 + 1, 1);
    float roi_h = (float)max(y2 - y1 + 1, 1);
    float bw = roi_w * (1.0f / PW);
    float bh = roi_h * (1.0f / PH);

    int hs = min(max((int)floorf((float)ph * bh) + y1, 0), HH);
    int he = min(max((int)ceilf((float)(ph + 1) * bh) + y1, 0), HH);
    int ws = min(max((int)floorf((float)pw * bw) + x1, 0), WW);
    int we = min(max((int)ceilf((float)(pw + 1) * bw) + x1, 0), WW);
    bool empty = (he <= hs) || (we <= ws);

    // lane covers channels c = chalf*64 + lane*2, c+1
    const float2* fT2 = reinterpret_cast<const float2*>(
        g_featT + ((long)b * HH * WW) * CC) + (chalf * 32 + lane);

    int wcnt = we - ws;   // <= MAXW
    const float2* base = fT2 + (long)ws * (CC / 2);

    float m0 = -FLT_MAX, m1 = -FLT_MAX;
    for (int h = hs; h < he; h++) {
        const float2* rowp = base + (long)(h * WW) * (CC / 2);
        float2 v[MAXW];
        #pragma unroll
        for (int i = 0; i < MAXW; i++) {
            v[i].x = -FLT_MAX;
            v[i].y = -FLT_MAX;
            if (i < wcnt) v[i] = __ldg(rowp + (long)i * (CC / 2));
        }
        #pragma unroll
        for (int i = 0; i < MAXW; i++) {
            m0 = fmaxf(m0, v[i].x);
            m1 = fmaxf(m1, v[i].y);
        }
    }
    if (empty) { m0 = 0.f; m1 = 0.f; }

    reinterpret_cast<float2*>(so + pw * CC)[chalf * 32 + lane] =
        make_float2(m0, m1);
    __syncthreads();

    // write 896 floats: out[k*6272 + c*49 + ph*7 + pw]
    float* ok = out + (long)k * (CC * PH * PW) + ph * PW;
    for (int e = threadIdx.x; e < CC * PW; e += blockDim.x) {
        int cc  = e / PW;
        int ppw = e % PW;
        ok[cc * (PH * PW) + ppw] = so[ppw * CC + cc];
    }
}

extern "C" void kernel_launch(void* const* d_in, const int* in_sizes, int n_in,
                              void* d_out, int out_size) {
    const float* feat = (const float*)d_in[0];
    const float* rois = (const float*)d_in[1];
    float* out = (float*)d_out;

    transpose_kernel<<<NN * HH * 2, 256>>>(feat);

    int K = in_sizes[1] / 5;   // 256
    roipool_kernel<<<K * PH, 448>>>(rois, out);
}

// round 7
// speedup vs baseline: 1.0077x; 1.0077x over previous
#include <cuda_runtime.h>
#include <cfloat>

#define PH 7
#define PW 7
#define NN 4
#define CC 128
#define HH 50
#define WW 50
#define KK 256
#define SCALE 0.0625f

// channel-last features [N][H][W][C], 5.12 MB
__device__ float g_featT[NN * HH * WW * CC];
// column maxes [k][h][pw][c], 45.9 MB (only ROI rows touched)
__device__ float g_colmax[KK * HH * PW * CC];
// per-ROI metadata
__device__ int g_b[KK], g_hlo[KK], g_hhi[KK];
__device__ int g_ws[KK][8], g_we[KK][8], g_hs[KK][8], g_he[KK][8];

__global__ void precompute_kernel(const float* __restrict__ rois, int K) {
    int k = blockIdx.x * blockDim.x + threadIdx.x;
    if (k >= K) return;
    const float* r = rois + k * 5;
    int b  = (int)r[0];
    int x1 = (int)rintf(r[1] * SCALE);
    int y1 = (int)rintf(r[2] * SCALE);
    int x2 = (int)rintf(r[3] * SCALE);
    int y2 = (int)rintf(r[4] * SCALE);
    float bw = (float)max(x2 - x1 + 1, 1) * (1.0f / PW);
    float bh = (float)max(y2 - y1 + 1, 1) * (1.0f / PH);
    g_b[k] = b;
    #pragma unroll
    for (int p = 0; p < PH; p++) {
        int hs = min(max((int)floorf((float)p * bh) + y1, 0), HH);
        int he = min(max((int)ceilf((float)(p + 1) * bh) + y1, 0), HH);
        int ws = min(max((int)floorf((float)p * bw) + x1, 0), WW);
        int we = min(max((int)ceilf((float)(p + 1) * bw) + x1, 0), WW);
        g_hs[k][p] = hs; g_he[k][p] = he;
        g_ws[k][p] = ws; g_we[k][p] = we;
    }
    g_hlo[k] = g_hs[k][0];
    g_hhi[k] = g_he[k][PH - 1];
}

// transpose [C,W] -> [W,C] per (b,h,c-half)
__global__ void transpose_kernel(const float* __restrict__ feat) {
    int blk = blockIdx.x;
    int b    = blk / (HH * 2);
    int rest = blk % (HH * 2);
    int h    = rest >> 1;
    int c0   = (rest & 1) * 64;

    __shared__ float tile[64 * WW];

    const float* src = feat + ((long)b * CC + c0) * (HH * WW) + h * WW;
    for (int i = threadIdx.x; i < 64 * WW; i += blockDim.x) {
        int c = i / WW;
        int w = i % WW;
        tile[i] = src[(long)c * (HH * WW) + w];
    }
    __syncthreads();
    float* dst = g_featT + ((long)(b * HH + h) * WW) * CC + c0;
    for (int i = threadIdx.x; i < 64 * WW; i += blockDim.x) {
        int w = i >> 6;
        int c = i & 63;
        dst[(long)w * CC + c] = tile[c * WW + w];
    }
}

// Pass A: colmax[k][h][pw][c] = max over w in bin. Block = (k, 4-row chunk).
// 448 threads: pw = tid/64 (warp-uniform), cp = tid%64 (float2 channels).
__global__ __launch_bounds__(448) void passA_kernel() {
    int k  = blockIdx.x;
    int hc = blockIdx.y;
    int hlo = g_hlo[k], hhi = g_hhi[k];
    int h0 = hc * 4;
    if (h0 >= hhi || h0 + 4 <= hlo) return;

    int pw = threadIdx.x >> 6;
    int cp = threadIdx.x & 63;
    int b  = g_b[k];
    int ws = g_ws[k][pw], we = g_we[k][pw];

    const float2* fbase = reinterpret_cast<const float2*>(g_featT)
                          + (long)b * (HH * WW * 64) + cp;
    // clamp rows so all 4 streams run the same trip count safely
    int hcl = max(hlo, 0);
    int hch = max(hhi - 1, hcl);
    int ha = min(max(h0 + 0, hcl), hch);
    int hb = min(max(h0 + 1, hcl), hch);
    int hcr = min(max(h0 + 2, hcl), hch);
    int hd = min(max(h0 + 3, hcl), hch);
    const float2* rp0 = fbase + (long)(ha * WW) * 64;
    const float2* rp1 = fbase + (long)(hb * WW) * 64;
    const float2* rp2 = fbase + (long)(hcr * WW) * 64;
    const float2* rp3 = fbase + (long)(hd * WW) * 64;

    float m0x = -FLT_MAX, m0y = -FLT_MAX, m1x = -FLT_MAX, m1y = -FLT_MAX;
    float m2x = -FLT_MAX, m2y = -FLT_MAX, m3x = -FLT_MAX, m3y = -FLT_MAX;

    for (int w = ws; w < we; w++) {
        long o = (long)w * 64;
        float2 v0 = __ldg(rp0 + o);
        float2 v1 = __ldg(rp1 + o);
        float2 v2 = __ldg(rp2 + o);
        float2 v3 = __ldg(rp3 + o);
        m0x = fmaxf(m0x, v0.x); m0y = fmaxf(m0y, v0.y);
        m1x = fmaxf(m1x, v1.x); m1y = fmaxf(m1y, v1.y);
        m2x = fmaxf(m2x, v2.x); m2y = fmaxf(m2y, v2.y);
        m3x = fmaxf(m3x, v3.x); m3y = fmaxf(m3y, v3.y);
    }

    float2* cm = reinterpret_cast<float2*>(g_colmax)
                 + ((long)k * HH * PW + pw) * 64 + cp;
    if (h0 + 0 >= hlo && h0 + 0 < hhi) cm[(long)(h0 + 0) * (PW * 64)] = make_float2(m0x, m0y);
    if (h0 + 1 >= hlo && h0 + 1 < hhi) cm[(long)(h0 + 1) * (PW * 64)] = make_float2(m1x, m1y);
    if (h0 + 2 >= hlo && h0 + 2 < hhi) cm[(long)(h0 + 2) * (PW * 64)] = make_float2(m2x, m2y);
    if (h0 + 3 >= hlo && h0 + 3 < hhi) cm[(long)(h0 + 3) * (PW * 64)] = make_float2(m3x, m3y);
}

// Pass B: out[k][c][ph][pw] = max over h of colmax. Block = (k, ph).
__global__ __launch_bounds__(448) void passB_kernel(float* __restrict__ out) {
    int k  = blockIdx.x;
    int ph = blockIdx.y;
    int pw = threadIdx.x >> 6;
    int cp = threadIdx.x & 63;

    __shared__ float2 so[PW * 64];  // [pw][cp]

    int hs = g_hs[k][ph], he = g_he[k][ph];
    int ws = g_ws[k][pw], we = g_we[k][pw];
    bool empty = (he <= hs) || (we <= ws);

    const float2* cm = reinterpret_cast<const float2*>(g_colmax)
                       + ((long)k * HH * PW + pw) * 64 + cp;

    float mx = -FLT_MAX, my = -FLT_MAX;
    int h = hs;
    for (; h + 1 < he; h += 2) {
        float2 a = __ldg(cm + (long)h * (PW * 64));
        float2 b2 = __ldg(cm + (long)(h + 1) * (PW * 64));
        mx = fmaxf(mx, fmaxf(a.x, b2.x));
        my = fmaxf(my, fmaxf(a.y, b2.y));
    }
    if (h < he) {
        float2 a = __ldg(cm + (long)h * (PW * 64));
        mx = fmaxf(mx, a.x);
        my = fmaxf(my, a.y);
    }
    if (empty) { mx = 0.f; my = 0.f; }

    so[pw * 64 + cp] = make_float2(mx, my);
    __syncthreads();

    const float* sof = reinterpret_cast<const float*>(so);  // [pw][128]
    float* ok = out + (long)k * (CC * PH * PW) + ph * PW;
    for (int e = threadIdx.x; e < CC * PW; e += 448) {
        int cc  = e / PW;
        int ppw = e % PW;
        ok[cc * (PH * PW) + ppw] = sof[ppw * CC + cc];
    }
}

extern "C" void kernel_launch(void* const* d_in, const int* in_sizes, int n_in,
                              void* d_out, int out_size) {
    const float* feat = (const float*)d_in[0];
    const float* rois = (const float*)d_in[1];
    float* out = (float*)d_out;
    int K = in_sizes[1] / 5;  // 256

    precompute_kernel<<<(K + 255) / 256, 256>>>(rois, K);
    transpose_kernel<<<NN * HH * 2, 256>>>(feat);
    passA_kernel<<<dim3(K, (HH + 3) / 4), 448>>>();
    passB_kernel<<<dim3(K, PH), 448>>>(out);
}

// round 9
// speedup vs baseline: 1.4204x; 1.4096x over previous
#include <cuda_runtime.h>
#include <cfloat>

#define PH 7
#define PW 7
#define NN 4
#define CC 128
#define HH 50
#define WW 50
#define SCALE 0.0625f

// channel-last features [N][H][W][C], 5.12 MB
__device__ float g_featT[NN * HH * WW * CC];

// transpose [C,W] -> [W,C] per (b,h,c-half)
__global__ void transpose_kernel(const float* __restrict__ feat) {
    int blk = blockIdx.x;
    int b    = blk / (HH * 2);
    int rest = blk % (HH * 2);
    int h    = rest >> 1;
    int c0   = (rest & 1) * 64;

    __shared__ float tile[64 * WW];

    const float* src = feat + ((long)b * CC + c0) * (HH * WW) + h * WW;
    for (int i = threadIdx.x; i < 64 * WW; i += blockDim.x) {
        int c = i / WW;
        int w = i % WW;
        tile[i] = src[(long)c * (HH * WW) + w];
    }
    __syncthreads();
    float* dst = g_featT + ((long)(b * HH + h) * WW) * CC + c0;
    for (int i = threadIdx.x; i < 64 * WW; i += blockDim.x) {
        int w = i >> 6;
        int c = i & 63;
        dst[(long)w * CC + c] = tile[c * WW + w];
    }
}

__device__ __forceinline__ float4 fmax4(float4 a, float4 b) {
    return make_float4(fmaxf(a.x, b.x), fmaxf(a.y, b.y),
                       fmaxf(a.z, b.z), fmaxf(a.w, b.w));
}

// One block per (k, ph). Phase 1: h-reduce each w column into smem (each
// feature cell read once). Phase 2: w-reduce from smem per pw bin.
__global__ __launch_bounds__(512) void roipool_kernel(const float* __restrict__ rois,
                                                      float* __restrict__ out) {
    int k  = blockIdx.x / PH;
    int ph = blockIdx.x % PH;
    int tid = threadIdx.x;

    __shared__ float rowmax[WW * CC];   // [w - ws0][c], 25.6 KB
    __shared__ float so[PW * CC];       // [pw][c], 3.5 KB

    const float* r = rois + k * 5;
    int b  = (int)__ldg(r + 0);
    int x1 = (int)rintf(__ldg(r + 1) * SCALE);
    int y1 = (int)rintf(__ldg(r + 2) * SCALE);
    int x2 = (int)rintf(__ldg(r + 3) * SCALE);
    int y2 = (int)rintf(__ldg(r + 4) * SCALE);

    int roi_wi = max(x2 - x1 + 1, 1);
    int roi_hi = max(y2 - y1 + 1, 1);
    float bw = (float)roi_wi * (1.0f / PW);
    float bh = (float)roi_hi * (1.0f / PH);

    int hs = min(max((int)floorf((float)ph * bh) + y1, 0), HH);
    int he = min(max((int)ceilf((float)(ph + 1) * bh) + y1, 0), HH);

    // w band covering ALL pw bins, using the SAME formulas as the bins
    // (ws(0) = clip(x1), we(PW-1) = clip(ceil(PW*bw)+x1)) — ceil(PW*bw) can
    // exceed roi_wi due to float rounding, so it must be computed, not assumed.
    int ws0 = min(max(x1, 0), WW);
    int we6 = min(max((int)ceilf((float)PW * bw) + x1, 0), WW);
    int cnt = we6 - ws0;

    // ---- Phase 1: h-reduce each w column (warp = w chunk, lane = 4ch) ----
    if (he > hs) {
        int wc   = tid >> 5;
        int lane = tid & 31;
        const float4* fb = reinterpret_cast<const float4*>(
            g_featT + ((long)b * HH * WW) * CC) + lane;
        int hlast = he - 1;
        for (int w = wc; w < cnt; w += 16) {
            const float4* col = fb + (long)(ws0 + w) * (CC / 4);
            float4 m = make_float4(-FLT_MAX, -FLT_MAX, -FLT_MAX, -FLT_MAX);
            int h = hs;
            for (; h + 1 < he; h += 2) {
                float4 a  = __ldg(col + (long)(h * WW) * (CC / 4));
                float4 b4 = __ldg(col + (long)((h + 1) * WW) * (CC / 4));
                m = fmax4(m, fmax4(a, b4));
            }
            if (h <= hlast) {
                float4 a = __ldg(col + (long)(h * WW) * (CC / 4));
                m = fmax4(m, a);
            }
            reinterpret_cast<float4*>(rowmax + w * CC)[lane] = m;
        }
    }
    __syncthreads();

    // ---- Phase 2: w-reduce per pw bin from smem ----
    if (tid < PW * 64) {
        int pw = tid >> 6;
        int cp = tid & 63;
        int ws = min(max((int)floorf((float)pw * bw) + x1, 0), WW);
        int we = min(max((int)ceilf((float)(pw + 1) * bw) + x1, 0), WW);
        bool empty = (he <= hs) || (we <= ws);

        float mx = -FLT_MAX, my = -FLT_MAX;
        if (!empty) {
            for (int w = ws; w < we; w++) {
                float2 v = reinterpret_cast<const float2*>(
                    rowmax + (w - ws0) * CC)[cp];
                mx = fmaxf(mx, v.x);
                my = fmaxf(my, v.y);
            }
        } else {
            mx = 0.f; my = 0.f;
        }
        reinterpret_cast<float2*>(so + pw * CC)[cp] = make_float2(mx, my);
    }
    __syncthreads();

    // ---- staged coalesced-ish output: out[k][c][ph][pw] ----
    float* ok = out + (long)k * (CC * PH * PW) + ph * PW;
    for (int e = tid; e < CC * PW; e += 512) {
        int cc  = e / PW;
        int ppw = e % PW;
        ok[cc * (PH * PW) + ppw] = so[ppw * CC + cc];
    }
}

extern "C" void kernel_launch(void* const* d_in, const int* in_sizes, int n_in,
                              void* d_out, int out_size) {
    const float* feat = (const float*)d_in[0];
    const float* rois = (const float*)d_in[1];
    float* out = (float*)d_out;
    int K = in_sizes[1] / 5;  // 256

    transpose_kernel<<<NN * HH * 2, 256>>>(feat);
    roipool_kernel<<<K * PH, 512>>>(rois, out);
}

// round 10
// speedup vs baseline: 1.5524x; 1.0929x over previous
#include <cuda_runtime.h>
#include <cfloat>

#define PH 7
#define PW 7
#define NN 4
#define CC 128
#define HH 50
#define WW 50
#define SCALE 0.0625f

// channel-last features [N][H][W][C], 5.12 MB
__device__ float g_featT[NN * HH * WW * CC];

// transpose [C,W] -> [W,C] per (b,h,c-half)
__global__ void transpose_kernel(const float* __restrict__ feat) {
    int blk = blockIdx.x;
    int b    = blk / (HH * 2);
    int rest = blk % (HH * 2);
    int h    = rest >> 1;
    int c0   = (rest & 1) * 64;

    __shared__ float tile[64 * WW];

    const float* src = feat + ((long)b * CC + c0) * (HH * WW) + h * WW;
    for (int i = threadIdx.x; i < 64 * WW; i += blockDim.x) {
        int c = i / WW;
        int w = i % WW;
        tile[i] = src[(long)c * (HH * WW) + w];
    }
    __syncthreads();
    float* dst = g_featT + ((long)(b * HH + h) * WW) * CC + c0;
    for (int i = threadIdx.x; i < 64 * WW; i += blockDim.x) {
        int w = i >> 6;
        int c = i & 63;
        dst[(long)w * CC + c] = tile[c * WW + w];
    }
}

__device__ __forceinline__ float4 fmax4(float4 a, float4 b) {
    return make_float4(fmaxf(a.x, b.x), fmaxf(a.y, b.y),
                       fmaxf(a.z, b.z), fmaxf(a.w, b.w));
}

// One block (256 thr) per (k, ph). Phase 1: h-reduce each w column into smem
// (each band cell read once). Phase 2: w-reduce per pw bin from smem (float4).
__global__ __launch_bounds__(256) void roipool_kernel(const float* __restrict__ rois,
                                                      float* __restrict__ out) {
    int k  = blockIdx.x / PH;
    int ph = blockIdx.x % PH;
    int tid = threadIdx.x;

    __shared__ float rowmax[WW * CC];   // [w - ws0][c], 25.6 KB
    __shared__ float so[PW * CC];       // [pw][c], 3.5 KB

    const float* r = rois + k * 5;
    int b  = (int)__ldg(r + 0);
    int x1 = (int)rintf(__ldg(r + 1) * SCALE);
    int y1 = (int)rintf(__ldg(r + 2) * SCALE);
    int x2 = (int)rintf(__ldg(r + 3) * SCALE);
    int y2 = (int)rintf(__ldg(r + 4) * SCALE);

    int roi_wi = max(x2 - x1 + 1, 1);
    int roi_hi = max(y2 - y1 + 1, 1);
    float bw = (float)roi_wi * (1.0f / PW);
    float bh = (float)roi_hi * (1.0f / PH);

    int hs = min(max((int)floorf((float)ph * bh) + y1, 0), HH);
    int he = min(max((int)ceilf((float)(ph + 1) * bh) + y1, 0), HH);

    // w band covering all pw bins, same formulas as the bins themselves
    int ws0 = min(max(x1, 0), WW);
    int we6 = min(max((int)ceilf((float)PW * bw) + x1, 0), WW);
    int cnt = we6 - ws0;

    // ---- Phase 1: h-reduce each w column (warp = w chunk, lane = 4ch) ----
    if (he > hs) {
        int wc   = tid >> 5;   // 0..7
        int lane = tid & 31;
        const float4* fb = reinterpret_cast<const float4*>(
            g_featT + ((long)b * HH * WW) * CC) + lane;
        for (int w = wc; w < cnt; w += 8) {
            const float4* col = fb + (long)(ws0 + w) * (CC / 4);
            float4 m = make_float4(-FLT_MAX, -FLT_MAX, -FLT_MAX, -FLT_MAX);
            int h = hs;
            for (; h + 1 < he; h += 2) {
                float4 a  = __ldg(col + (long)(h * WW) * (CC / 4));
                float4 b4 = __ldg(col + (long)((h + 1) * WW) * (CC / 4));
                m = fmax4(m, fmax4(a, b4));
            }
            if (h < he) {
                float4 a = __ldg(col + (long)(h * WW) * (CC / 4));
                m = fmax4(m, a);
            }
            reinterpret_cast<float4*>(rowmax + w * CC)[lane] = m;
        }
    }
    __syncthreads();

    // ---- Phase 2: w-reduce per pw bin from smem (float4 lanes) ----
    if (tid < PW * 32) {
        int pw = tid >> 5;
        int cp = tid & 31;
        int ws = min(max((int)floorf((float)pw * bw) + x1, 0), WW);
        int we = min(max((int)ceilf((float)(pw + 1) * bw) + x1, 0), WW);
        bool empty = (he <= hs) || (we <= ws);

        float4 m = make_float4(-FLT_MAX, -FLT_MAX, -FLT_MAX, -FLT_MAX);
        if (!empty) {
            for (int w = ws; w < we; w++) {
                float4 v = reinterpret_cast<const float4*>(
                    rowmax + (w - ws0) * CC)[cp];
                m = fmax4(m, v);
            }
        } else {
            m = make_float4(0.f, 0.f, 0.f, 0.f);
        }
        reinterpret_cast<float4*>(so + pw * CC)[cp] = m;
    }
    __syncthreads();

    // ---- staged output: out[k][c][ph][pw] ----
    float* ok = out + (long)k * (CC * PH * PW) + ph * PW;
    for (int e = tid; e < CC * PW; e += 256) {
        int cc  = e / PW;
        int ppw = e % PW;
        ok[cc * (PH * PW) + ppw] = so[ppw * CC + cc];
    }
}

extern "C" void kernel_launch(void* const* d_in, const int* in_sizes, int n_in,
                              void* d_out, int out_size) {
    const float* feat = (const float*)d_in[0];
    const float* rois = (const float*)d_in[1];
    float* out = (float*)d_out;
    int K = in_sizes[1] / 5;  // 256

    transpose_kernel<<<NN * HH * 2, 256>>>(feat);
    roipool_kernel<<<K * PH, 256>>>(rois, out);
}